// round 13
// baseline (speedup 1.0000x reference)
#include <cuda_runtime.h>
#include <cuda_fp16.h>
#include <cstdint>

#define HH 96
#define WW 96
#define NPIX (HH*WW)
#define PADW 100
#define PPIX 9800   // 98 rows x 100 cols, interior (y,x) -> (y+1)*100 + (x+2)

// ---------------- scratch (static device globals; no allocation) ----------------
// Activations are CHANNEL-MINOR: buf[n][padpix][ch], fp16.
__device__ __half g_xh[4*PPIX*128];     // ch 0-63: x, ch 64-127: h
__device__ float  g_c[4*64*NPIX];       // cell state (f32, [n][ch][pix])
__device__ __half g_comb[4*PPIX*64];    // fuse conv output
__device__ float  g_om[4*216*NPIX];     // offset/mask conv output (f32, [n][ch][pix])
__device__ __half g_sampt[4*576*NPIX];  // DCN sampled matrix, [n][k][pix] fp16
__device__ __half g_fused[4*PPIX*128];  // DCN output, relu
__device__ float  g_cc[4*256*NPIX];     // gate conv output (f32, [n][ch][pix])
__device__ __half g_fb[10*PPIX*128];    // cat input: ch0-63 fwd h, ch64-127 bwd h
__device__ __half g_wh[640512];         // all weights fp16 (conv weights r-major)

// weight offsets in g_wh
#define WF_FUSE 0
#define WF_OM   73728
#define WF_DCN  198144
#define WF_CC   271872
#define WF_CAT  566784

__device__ __forceinline__ float sigf(float x){ return 1.f / (1.f + __expf(-x)); }

__device__ __forceinline__ uint32_t s2u(const void* p){
    uint32_t a;
    asm("{ .reg .u64 t; cvta.to.shared.u64 t, %1; cvt.u32.u64 %0, t; }" : "=r"(a) : "l"(p));
    return a;
}
__device__ __forceinline__ void ldsm4(uint32_t r[4], uint32_t addr){
    asm volatile("ldmatrix.sync.aligned.m8n8.x4.shared.b16 {%0,%1,%2,%3}, [%4];"
        : "=r"(r[0]), "=r"(r[1]), "=r"(r[2]), "=r"(r[3]) : "r"(addr));
}
__device__ __forceinline__ void mma16(float c[4], const uint32_t a[4], uint32_t b0, uint32_t b1){
    asm volatile(
        "mma.sync.aligned.m16n8k16.row.col.f32.f16.f16.f32 "
        "{%0,%1,%2,%3}, {%4,%5,%6,%7}, {%8,%9}, {%0,%1,%2,%3};"
        : "+f"(c[0]), "+f"(c[1]), "+f"(c[2]), "+f"(c[3])
        : "r"(a[0]), "r"(a[1]), "r"(a[2]), "r"(a[3]), "r"(b0), "r"(b1));
}

static constexpr int SMEM_GEMM_TOTAL = 65536;

// ================= f16 HMMA implicit-GEMM =================
// D[n][co][pix] = sum_k W[co][k] * Im[pix][k]  (+bias, opt relu)
// MT: co tile (128 or 64). Warp grid 4co x 2px (MT=128) or 2co x 4px (MT=64).
// MODE 0: conv3x3 over CH-MINOR padded fp16 buffer; k = r*Cin + cin (weights
//         pre-permuted). Cin = 1<<cinlog. Quarter = 2 x LDG.128, no pack ALU.
// MODE 1: Im[pix][k] = in0[n][k][pix]  ([k][pix] fp16)
// OUTM 0: f32 flat [n][Cout][NPIX] ; 1: fp16 ch-minor padded [n][padpix][ochs]
// OUTM 2: f32 flat with n=t*2+b -> [(b*5+t)][co][NPIX]
template<int MT, int MODE, int ACT, int OUTM>
__global__ __launch_bounds__(256, 2) void tgemm(
    const __half* __restrict__ in0, long s0, int cinlog,
    const __half* __restrict__ wh, const float* __restrict__ bias,
    void* __restrict__ out, long oLane, int ochs, int Cout, int K)
{
    constexpr int NB = (MT == 128) ? 4 : 2;   // B n16-tiles per warp
    extern __shared__ char dsm[];
    const uint32_t sb = s2u(dsm);
    const int tid = threadIdx.x;
    const int wid = tid >> 5;
    const int lid = tid & 31;
    const int n   = blockIdx.z;
    const int p0  = blockIdx.x * 128;
    const int co0 = blockIdx.y * MT;

    // ---- staging role: tid<128 stages B row (pixel), tid>=128 stages A row (cout)
    const bool isB = (tid < 128);
    const int  srow = isB ? tid : (tid - 128);
    const bool act  = isB || (srow < MT);
    const int  spg = p0 + srow;
    const int  spy = spg / WW;
    const int  spx = spg - spy * WW;
    const int  sco = co0 + srow;
    const bool wok = (sco < Cout) && (srow < MT);
    // B mode0: ch-minor padded base at this pixel ; mode1: [k][pix] base
    const unsigned short* laneB0 =
        (const unsigned short*)(in0 + (long)n * s0)
        + ((long)((spy + 1) * PADW + spx + 2) << cinlog);
    const unsigned short* laneB1 =
        (const unsigned short*)(in0 + (long)n * s0) + spg;
    const uint4* wrow = (const uint4*)(wh + (long)sco * K);
    const uint32_t stsRole = sb + (isB ? 32768u : 0u) + (uint32_t)srow * 128u;
    const int  sr7 = srow & 7;

    unsigned hv[16];   // B mode1 raw u16 quarter
    unsigned st[8];    // staged u32 quarter

    // load one quarter (16 k's): kk0 = chunk*64 + q*16
    auto ldgQ = [&](int kk0) {
        if (isB) {
            if (MODE == 0) {
                const int r    = kk0 >> cinlog;
                const int cinb = kk0 & ((1 << cinlog) - 1);
                const int dy   = r / 3;
                const int dx   = r - dy * 3;
                const uint4* bt = (const uint4*)
                    (laneB0 + (((dy - 1) * PADW + (dx - 1)) << cinlog) + cinb);
                uint4 q0 = __ldg(bt);
                uint4 q1 = __ldg(bt + 1);
                st[0]=q0.x; st[1]=q0.y; st[2]=q0.z; st[3]=q0.w;
                st[4]=q1.x; st[5]=q1.y; st[6]=q1.z; st[7]=q1.w;
            } else {
                const unsigned short* bt = laneB1 + (long)kk0 * NPIX;
#pragma unroll
                for (int j = 0; j < 16; j++)
                    hv[j] = __ldg(bt + (long)j * NPIX);
            }
        } else if (act) {
            if (wok) {
                const uint4* wp = wrow + (kk0 >> 3);
                uint4 q0 = __ldg(wp);
                uint4 q1 = __ldg(wp + 1);
                st[0]=q0.x; st[1]=q0.y; st[2]=q0.z; st[3]=q0.w;
                st[4]=q1.x; st[5]=q1.y; st[6]=q1.z; st[7]=q1.w;
            } else {
#pragma unroll
                for (int j = 0; j < 8; j++) st[j] = 0u;
            }
        }
    };
    // store quarter q of buffer b (16 k -> groups cg=2q, 2q+1)
    auto stsQ = [&](int b, int q) {
        if (!act) return;
        if (isB && MODE == 1) {
#pragma unroll
            for (int j = 0; j < 8; j++)
                st[j] = hv[2*j] | (hv[2*j + 1] << 16);
        }
        uint32_t base = stsRole + (uint32_t)b * 16384u;
#pragma unroll
        for (int c = 0; c < 2; c++) {
            int cg = 2*q + c;
            uint32_t addr = base + (uint32_t)((cg ^ sr7) << 4);
            asm volatile("st.shared.v4.b32 [%0], {%1, %2, %3, %4};"
                :: "r"(addr), "r"(st[4*c]), "r"(st[4*c+1]), "r"(st[4*c+2]), "r"(st[4*c+3])
                : "memory");
        }
    };

    // ---- compute-side ldmatrix geometry
    const int lr = lid & 7;
    const int q  = lid >> 3;
    const int wco = (MT == 128) ? (wid >> 1) * 32 : (wid >> 2) * 32;
    const int wpx = (MT == 128) ? (wid & 1) * 64  : (wid & 3) * 32;
    uint32_t offA[2]; int r7A[2]; const int kselA = q >> 1;
#pragma unroll
    for (int m = 0; m < 2; m++) {
        int r = wco + 16*m + (q & 1)*8 + lr;
        offA[m] = (uint32_t)r * 128u;  r7A[m] = r & 7;
    }
    uint32_t offB[NB]; int r7B[NB]; const int kselB = q & 1;
#pragma unroll
    for (int j = 0; j < NB; j++) {
        int r = wpx + 16*j + (q >> 1)*8 + lr;
        offB[j] = (uint32_t)r * 128u;  r7B[j] = r & 7;
    }

    float acc[2][2*NB][4];
#pragma unroll
    for (int m = 0; m < 2; m++)
#pragma unroll
        for (int j = 0; j < 2*NB; j++)
#pragma unroll
            for (int v = 0; v < 4; v++) acc[m][j][v] = 0.f;

    // one k16 MMA step s (0..3) on buffer b
    auto compute_s = [&](int b, int s) {
        const uint32_t abase = sb + (uint32_t)b * 16384u;
        const uint32_t bbase = sb + 32768u + (uint32_t)b * 16384u;
        uint32_t Af[2][4];
#pragma unroll
        for (int m = 0; m < 2; m++)
            ldsm4(Af[m], abase + offA[m] + (uint32_t)(((2*s + kselA) ^ r7A[m]) << 4));
#pragma unroll
        for (int j = 0; j < NB; j++) {
            uint32_t Bf[4];
            ldsm4(Bf, bbase + offB[j] + (uint32_t)(((2*s + kselB) ^ r7B[j]) << 4));
#pragma unroll
            for (int m = 0; m < 2; m++) {
                mma16(acc[m][2*j],     Af[m], Bf[0], Bf[1]);
                mma16(acc[m][2*j + 1], Af[m], Bf[2], Bf[3]);
            }
        }
    };

    // ---- pipeline: K-chunks of 64, double buffered, quarters interleaved
    const int nch = K / 64;
#pragma unroll
    for (int qq = 0; qq < 4; qq++) { ldgQ(qq * 16); stsQ(0, qq); }
    __syncthreads();
    for (int i = 0; i < nch; i++) {
        const int b = i & 1, nb = b ^ 1;
        const bool more = (i + 1 < nch);
        const int nk = (i + 1) * 64;
        if (more) ldgQ(nk);
        compute_s(b, 0);
        if (more) { stsQ(nb, 0); ldgQ(nk + 16); }
        compute_s(b, 1);
        if (more) { stsQ(nb, 1); ldgQ(nk + 32); }
        compute_s(b, 2);
        if (more) { stsQ(nb, 2); ldgQ(nk + 48); }
        compute_s(b, 3);
        if (more) stsQ(nb, 3);
        __syncthreads();
    }

    // ---- epilogue
    const int g2 = lid >> 2;
    const int tg = lid & 3;
#pragma unroll
    for (int m = 0; m < 2; m++) {
        int cobase = co0 + wco + 16 * m + g2;
#pragma unroll
        for (int half = 0; half < 2; half++) {
            int co = cobase + 8 * half;
            if (co >= Cout) continue;
            float bsv = bias[co];
#pragma unroll
            for (int j = 0; j < 2*NB; j++) {
                float ox = acc[m][j][2*half]     + bsv;
                float oy = acc[m][j][2*half + 1] + bsv;
                if (ACT) { ox = fmaxf(ox, 0.f); oy = fmaxf(oy, 0.f); }
                int pix = p0 + wpx + 2*tg + 8*j;
                if (OUTM == 1) {
                    int y = pix / WW, x = pix - y * WW;
                    long pp = (long)(y + 1) * PADW + x + 2;
                    __half* oh = (__half*)out + (long)n * oLane + pp * ochs + co;
                    oh[0]    = __float2half(ox);
                    oh[ochs] = __float2half(oy);   // pix+1 same image row (pix even)
                } else {
                    long ob;
                    if (OUTM == 2) {
                        int bb = n & 1, tt = n >> 1;
                        ob = ((long)(bb * 5 + tt) * Cout + co) * NPIX + pix;
                    } else {
                        ob = ((long)n * Cout + co) * NPIX + pix;
                    }
                    *(float2*)((float*)out + ob) = make_float2(ox, oy);
                }
            }
        }
    }
}

// ---------------- weight convert kernels ----------------
__global__ void wperm(const float* __restrict__ w, __half* __restrict__ o, int Cin, int tot)
{
    int id = blockIdx.x * 256 + threadIdx.x;
    if (id >= tot) return;
    int r  = id % 9;
    int t2 = id / 9;
    int cin = t2 % Cin;
    int co  = t2 / Cin;
    o[(long)co * Cin * 9 + r * Cin + cin] = __float2half(w[id]);
}
__global__ void wplain(const float* __restrict__ w, __half* __restrict__ o, int tot)
{
    int id = blockIdx.x * 256 + threadIdx.x;
    if (id >= tot) return;
    o[id] = __float2half(w[id]);
}

// ---------------- stage x -> ch-minor padded fp16 (SMEM transpose) ----------------
__global__ void stage_x(const float* __restrict__ inp, int t)
{
    __shared__ __half sm[64][72];
    const int blk = blockIdx.x;          // 4 n x 144 pixel-tiles
    const int n  = blk / 144;
    const int p0 = (blk - n * 144) * 64;
    const int b  = n & 1;
    const int ts = (n < 2) ? t : (4 - t);
    const float* src = inp + (long)(b * 5 + ts) * 64 * NPIX;
    const int tid = threadIdx.x;
#pragma unroll
    for (int e = 0; e < 16; e++) {
        int flat = e * 256 + tid;
        int ch = flat >> 6, pl = flat & 63;
        sm[pl][ch] = __float2half(src[(long)ch * NPIX + p0 + pl]);
    }
    __syncthreads();
    __half* dst = g_xh + (long)n * PPIX * 128;
#pragma unroll
    for (int e = 0; e < 2; e++) {
        int u  = e * 256 + tid;
        int pl = u >> 3, c8 = (u & 7) * 8;
        int p  = p0 + pl;
        int py = p / WW, px = p - py * WW;
        long pp = (long)(py + 1) * PADW + px + 2;
        *(uint4*)(dst + pp * 128 + c8) = *(const uint4*)&sm[pl][c8];
    }
}

// ---------------- DCN bilinear sampler -> [n][k][pix] fp16 ----------------
__global__ void dcn_sample(const float* __restrict__ om, __half* __restrict__ sampt)
{
    int id = blockIdx.x * blockDim.x + threadIdx.x;   // 4*8*9*NPIX
    int p  = id % NPIX;
    int r  = id / NPIX;
    int kk = r % 9;  r /= 9;
    int g  = r % 8;
    int n  = r / 8;

    const float* omb = om + (long)n * 216 * NPIX;
    float offy = omb[((g * 9 + kk) * 2 + 0) * NPIX + p];
    float offx = omb[((g * 9 + kk) * 2 + 1) * NPIX + p];
    float m    = sigf(omb[(144 + g * 9 + kk) * NPIX + p]);

    int y  = p / WW;
    int x  = p - y * WW;
    int ky = kk / 3;
    int kx = kk - ky * 3;
    float py = (float)(y + ky - 1) + offy;
    float px = (float)(x + kx - 1) + offx;
    float fy = floorf(py), fx = floorf(px);
    float wy = py - fy,    wx = px - fx;
    int y0 = (int)fy, x0 = (int)fx;
    int y1 = y0 + 1,  x1 = x0 + 1;

    bool vy0 = (y0 >= 0) & (y0 < HH);
    bool vy1 = (y1 >= 0) & (y1 < HH);
    bool vx0 = (x0 >= 0) & (x0 < WW);
    bool vx1 = (x1 >= 0) & (x1 < WW);
    float w00 = (1.f - wy) * (1.f - wx) * (float)(vy0 && vx0);
    float w01 = (1.f - wy) * wx         * (float)(vy0 && vx1);
    float w10 = wy * (1.f - wx)         * (float)(vy1 && vx0);
    float w11 = wy * wx                 * (float)(vy1 && vx1);

    int cy0 = min(max(y0, 0), HH - 1), cy1 = min(max(y1, 0), HH - 1);
    int cx0 = min(max(x0, 0), WW - 1), cx1 = min(max(x1, 0), WW - 1);
    long i00 = (long)(cy0 + 1) * PADW + cx0 + 2, i01 = (long)(cy0 + 1) * PADW + cx1 + 2;
    long i10 = (long)(cy1 + 1) * PADW + cx0 + 2, i11 = (long)(cy1 + 1) * PADW + cx1 + 2;

    // ch-minor h: 8 contiguous channels per corner -> 1 x LDG.128 each
    const __half* hb = g_xh + (long)n * PPIX * 128 + 64 + g * 8;
    uint4 q00 = *(const uint4*)(hb + i00 * 128);
    uint4 q01 = *(const uint4*)(hb + i01 * 128);
    uint4 q10 = *(const uint4*)(hb + i10 * 128);
    uint4 q11 = *(const uint4*)(hb + i11 * 128);
    const __half* h00 = (const __half*)&q00;
    const __half* h01 = (const __half*)&q01;
    const __half* h10 = (const __half*)&q10;
    const __half* h11 = (const __half*)&q11;

    __half* op = sampt + ((long)n * 576 + (long)(g * 8) * 9 + kk) * NPIX + p;
#pragma unroll
    for (int cg = 0; cg < 8; cg++) {
        float v = w00 * __half2float(h00[cg]) + w01 * __half2float(h01[cg])
                + w10 * __half2float(h10[cg]) + w11 * __half2float(h11[cg]);
        op[(long)cg * 9 * NPIX] = __float2half(v * m);
    }
}

// ---------------- LSTM pointwise update (SMEM transpose for ch-minor h) ----------------
__global__ void lstm_k(const float* __restrict__ cc, float* __restrict__ cbuf, int t)
{
    __shared__ __half sm[64][72];
    const int blk = blockIdx.x;          // 4 n x 144 pixel-tiles
    const int n  = blk / 144;
    const int p0 = (blk - n * 144) * 64;
    const int tid = threadIdx.x;
    const float* c4 = cc + (long)n * 256 * NPIX;
    float* cbase = cbuf + (long)n * 64 * NPIX;
#pragma unroll
    for (int e = 0; e < 16; e++) {
        int flat = e * 256 + tid;
        int ch = flat >> 6, pl = flat & 63;
        long idx = (long)ch * NPIX + p0 + pl;
        float ci = c4[idx];
        float cf = c4[64 * NPIX + idx];
        float co = c4[128 * NPIX + idx];
        float cg = c4[192 * NPIX + idx];
        float c  = cbase[idx];
        float c2 = sigf(cf) * c + sigf(ci) * tanhf(cg);
        float h2 = sigf(co) * tanhf(c2);
        cbase[idx] = c2;
        sm[pl][ch] = __float2half(h2);
    }
    __syncthreads();
    __half* xdst = g_xh + (long)n * PPIX * 128 + 64;
    const int t2b = (n < 2) ? (t * 2 + n) : ((4 - t) * 2 + (n - 2));
    __half* fdst = g_fb + (long)t2b * PPIX * 128 + ((n < 2) ? 0 : 64);
#pragma unroll
    for (int e = 0; e < 2; e++) {
        int u  = e * 256 + tid;
        int pl = u >> 3, c8 = (u & 7) * 8;
        int p  = p0 + pl;
        int py = p / WW, px = p - py * WW;
        long pp = (long)(py + 1) * PADW + px + 2;
        uint4 v = *(const uint4*)&sm[pl][c8];
        *(uint4*)(xdst + pp * 128 + c8) = v;
        *(uint4*)(fdst + pp * 128 + c8) = v;
    }
}

// ---------------- host orchestration (graph-capturable) ----------------
extern "C" void kernel_launch(void* const* d_in, const int* in_sizes, int n_in,
                              void* d_out, int out_size)
{
    (void)in_sizes; (void)n_in; (void)out_size;
    const float* inp    = (const float*)d_in[0];
    const float* fuse_w = (const float*)d_in[1];
    const float* fuse_b = (const float*)d_in[2];
    const float* om_w   = (const float*)d_in[3];
    const float* om_b   = (const float*)d_in[4];
    const float* dcn_w  = (const float*)d_in[5];
    const float* dcn_b  = (const float*)d_in[6];
    const float* conv_w = (const float*)d_in[7];
    const float* conv_b = (const float*)d_in[8];
    const float* cat_w  = (const float*)d_in[9];
    const float* cat_b  = (const float*)d_in[10];

    __half *xh, *comb, *sampt, *fub, *fb, *wh;
    float *cb, *omb, *ccb;
    cudaGetSymbolAddress((void**)&xh,    g_xh);
    cudaGetSymbolAddress((void**)&cb,    g_c);
    cudaGetSymbolAddress((void**)&comb,  g_comb);
    cudaGetSymbolAddress((void**)&omb,   g_om);
    cudaGetSymbolAddress((void**)&sampt, g_sampt);
    cudaGetSymbolAddress((void**)&fub,   g_fused);
    cudaGetSymbolAddress((void**)&ccb,   g_cc);
    cudaGetSymbolAddress((void**)&fb,    g_fb);
    cudaGetSymbolAddress((void**)&wh,    g_wh);

    cudaFuncSetAttribute(tgemm<64,0,0,1>,  cudaFuncAttributeMaxDynamicSharedMemorySize, SMEM_GEMM_TOTAL);
    cudaFuncSetAttribute(tgemm<128,0,0,0>, cudaFuncAttributeMaxDynamicSharedMemorySize, SMEM_GEMM_TOTAL);
    cudaFuncSetAttribute(tgemm<128,1,1,1>, cudaFuncAttributeMaxDynamicSharedMemorySize, SMEM_GEMM_TOTAL);
    cudaFuncSetAttribute(tgemm<64,0,0,2>,  cudaFuncAttributeMaxDynamicSharedMemorySize, SMEM_GEMM_TOTAL);

    // weight converts (fp16, conv weights r-major permuted)
    wperm <<<288, 256>>>(fuse_w, wh + WF_FUSE, 128, 64*128*9);
    wperm <<<486, 256>>>(om_w,   wh + WF_OM,    64, 216*64*9);
    wplain<<<288, 256>>>(dcn_w,  wh + WF_DCN,       128*576);
    wperm <<<1152,256>>>(conv_w, wh + WF_CC,   128, 256*128*9);
    wperm <<<288, 256>>>(cat_w,  wh + WF_CAT,  128, 64*128*9);

    // zero padded buffers (borders must be 0) + cell state
    cudaMemsetAsync(xh,   0, sizeof(__half) * 4  * 128 * PPIX);
    cudaMemsetAsync(comb, 0, sizeof(__half) * 4  * 64  * PPIX);
    cudaMemsetAsync(fub,  0, sizeof(__half) * 4  * 128 * PPIX);
    cudaMemsetAsync(fb,   0, sizeof(__half) * 10 * 128 * PPIX);
    cudaMemsetAsync(cb,   0, sizeof(float)  * 4  * 64  * NPIX);

    for (int t = 0; t < 5; t++) {
        stage_x<<<576, 256>>>(inp, t);
        // combined = conv3x3(concat(x,h)) : Cin=128, Cout=64 -> ch-minor fp16
        tgemm<64,0,0,1><<<dim3(72, 1, 4), 256, SMEM_GEMM_TOTAL>>>(
            xh, 128L*PPIX, 7, wh + WF_FUSE, fuse_b, comb, 64L*PPIX, 64, 64, 1152);
        // om = conv3x3(combined) : Cin=64, Cout=216 -> f32 flat
        tgemm<128,0,0,0><<<dim3(72, 2, 4), 256, SMEM_GEMM_TOTAL>>>(
            comb, 64L*PPIX, 6, wh + WF_OM, om_b, omb, 0, 0, 216, 576);
        // DCN sampling -> [n][576][NPIX] fp16
        dcn_sample<<<(4*8*9*NPIX)/256, 256>>>(omb, sampt);
        // fused = relu(W_dcn @ sampled) : dense K=576 -> ch-minor fp16
        tgemm<128,1,1,1><<<dim3(72, 1, 4), 256, SMEM_GEMM_TOTAL>>>(
            sampt, 576L*NPIX, 0, wh + WF_DCN, dcn_b, fub, 128L*PPIX, 128, 128, 576);
        // cc = conv3x3(fused) : Cin=128, Cout=256 -> f32 flat
        tgemm<128,0,0,0><<<dim3(72, 2, 4), 256, SMEM_GEMM_TOTAL>>>(
            fub, 128L*PPIX, 7, wh + WF_CC, conv_b, ccb, 0, 0, 256, 1152);
        // LSTM gates + state update (writes h into xh and fb, ch-minor)
        lstm_k<<<576, 256>>>(ccb, cb, t);
    }

    // out[b][t] = conv3x3(concat(fwd,bwd)) over all 10 (t,b) lanes (M64 tile)
    tgemm<64,0,0,2><<<dim3(72, 1, 10), 256, SMEM_GEMM_TOTAL>>>(
        fb, 128L*PPIX, 7, wh + WF_CAT, cat_b, d_out, 0, 0, 64, 1152);
}